// round 6
// baseline (speedup 1.0000x reference)
#include <cuda_runtime.h>
#include <cstdint>

#define NN 10000
#define EE 300000
#define WD 32
#define DEPTH 4
#define ACOLS 8224           // 8192 (A) + 32 (bias part)
#define MST 36               // m smem row stride
#define HST 68               // Hs stride: multiple of 4 (float4-aligned)

// ---------------- scratch (static __device__) ----------------
__device__ __align__(16) float g_K2[EE * 256];          // relu MLP out, PERMUTED by col-bucket
__device__ __align__(16) float g_A[NN * ACOLS];         // per-node A|bias
__device__ __align__(16) float g_AW[32 * ACOLS];        // transposed ker3 weights
__device__ __align__(16) float g_H[NN * WD];
__device__ __align__(16) float g_AGG[NN * WD];
__device__ __align__(16) float g_COORD[NN * 3];
__device__ __align__(16) float g_CD[NN * 3];
__device__ float g_CNT[NN];
__device__ int   g_colcnt[NN];
__device__ int   g_rowcnt[NN];
__device__ int   g_coloff[NN + 1];
__device__ int   g_cur[NN];
__device__ int   g_pos[EE];     // edge -> sorted position
__device__ int   g_rows[EE];    // sorted position -> row node

// ---------------- setup ----------------
__global__ void k_hist(const int* __restrict__ ei) {
    int e = blockIdx.x * blockDim.x + threadIdx.x;
    if (e < EE) {
        atomicAdd(&g_rowcnt[ei[e]], 1);
        atomicAdd(&g_colcnt[ei[EE + e]], 1);
    }
}

__global__ void k_scan() {
    __shared__ int sh[1024];
    __shared__ int carry;
    int t = threadIdx.x;
    if (t == 0) carry = 0;
    __syncthreads();
    for (int base = 0; base < NN; base += 1024) {
        int v = (base + t < NN) ? g_colcnt[base + t] : 0;
        sh[t] = v;
        __syncthreads();
        for (int off = 1; off < 1024; off <<= 1) {
            int y = (t >= off) ? sh[t - off] : 0;
            __syncthreads();
            sh[t] += y;
            __syncthreads();
        }
        int incl = sh[t];
        if (base + t < NN) {
            int ex = carry + incl - v;
            g_coloff[base + t] = ex;
            g_cur[base + t] = ex;
        }
        int tot = sh[1023];
        __syncthreads();
        if (t == 0) carry += tot;
        __syncthreads();
    }
    if (t == 0) g_coloff[NN] = carry;
}

__global__ void k_scatter(const int* __restrict__ ei) {
    int e = blockIdx.x * blockDim.x + threadIdx.x;
    if (e < EE) {
        int r = ei[e], c = ei[EE + e];
        int p = atomicAdd(&g_cur[c], 1);
        g_pos[e] = p;
        g_rows[p] = r;
    }
}

__global__ void k_init(const float* __restrict__ x, const float* __restrict__ coords,
                       const float* __restrict__ fc1w, const float* __restrict__ fc1b) {
    int i = blockIdx.x * blockDim.x + threadIdx.x;
    if (i < NN) g_CNT[i] = fmaxf(1.f, (float)g_rowcnt[i]);
    if (i < NN * 3) g_COORD[i] = coords[i];
    if (i < NN * WD) {
        int n = i / WD, o = i % WD;
        float a = fc1b[o];
        #pragma unroll
        for (int j = 0; j < 3; j++) a += x[n * 3 + j] * fc1w[j * WD + o];
        g_H[i] = a;
    }
}

__global__ void k_cleanup() {
    int i = blockIdx.x * blockDim.x + threadIdx.x;
    if (i < NN) { g_colcnt[i] = 0; g_rowcnt[i] = 0; }
}

// ---------------- fused kernel MLP: K2 = relu(relu(ea@W1+b1)@W2+b2), permuted write ----
// Warp shape: 8 warps as 2x4; lanes as 4x8 (rowgrp = lane>>3, colgrp = lane&7).
__global__ void __launch_bounds__(256) k_gemm2(const float* __restrict__ ea,
                                               const float* __restrict__ w1,
                                               const float* __restrict__ b1,
                                               const float* __restrict__ w2,
                                               const float* __restrict__ b2) {
    extern __shared__ float s2[];
    float* R1t = s2;            // [128][64] k-major
    float* Bs  = s2 + 8192;     // [16][256]
    __shared__ float eas[64 * 6];
    __shared__ float w1s[6 * 128];
    __shared__ float b1s[128];
    int tid = threadIdx.x;
    int m0 = blockIdx.x * 64;

    for (int i = tid; i < 64 * 6; i += 256) {
        int g = m0 * 6 + i;
        eas[i] = (g < EE * 6) ? ea[g] : 0.f;
    }
    for (int i = tid; i < 768; i += 256) w1s[i] = w1[i];
    if (tid < 128) b1s[tid] = b1[tid];
    __syncthreads();

    // R1 tile: thread handles row r = tid&63, k-group tid>>6 (32 k's)
    {
        int r = tid & 63, kg = tid >> 6;
        float ev[6];
        #pragma unroll
        for (int j = 0; j < 6; j++) ev[j] = eas[r * 6 + j];
        #pragma unroll
        for (int q = 0; q < 32; q++) {
            int k = kg * 32 + q;
            float a = b1s[k];
            #pragma unroll
            for (int j = 0; j < 6; j++) a += ev[j] * w1s[j * 128 + k];
            R1t[k * 64 + r] = fmaxf(a, 0.f);
        }
    }
    __syncthreads();

    int wrp = tid >> 5, lane = tid & 31;
    int rowoff = (wrp >> 2) * 32 + (lane >> 3) * 8;   // 0..56
    int coloff = (wrp & 3) * 64 + (lane & 7) * 8;     // 0..248
    float acc[8][8];
    #pragma unroll
    for (int i = 0; i < 8; i++)
        #pragma unroll
        for (int j = 0; j < 8; j++) acc[i][j] = 0.f;

    for (int kc = 0; kc < 128; kc += 16) {
        #pragma unroll
        for (int i = 0; i < 4; i++) {
            int idx = tid + i * 256;
            int kk = idx >> 6, c4 = idx & 63;
            *(float4*)&Bs[kk * 256 + c4 * 4] = *(const float4*)&w2[(kc + kk) * 256 + c4 * 4];
        }
        __syncthreads();
        #pragma unroll
        for (int kk = 0; kk < 16; kk++) {
            float a[8], b[8];
            *(float4*)a       = *(float4*)&R1t[(kc + kk) * 64 + rowoff];
            *(float4*)(a + 4) = *(float4*)&R1t[(kc + kk) * 64 + rowoff + 4];
            *(float4*)b       = *(float4*)&Bs[kk * 256 + coloff];
            *(float4*)(b + 4) = *(float4*)&Bs[kk * 256 + coloff + 4];
            #pragma unroll
            for (int i = 0; i < 8; i++)
                #pragma unroll
                for (int j = 0; j < 8; j++) acc[i][j] += a[i] * b[j];
        }
        __syncthreads();
    }
    float bb[8];
    #pragma unroll
    for (int j = 0; j < 8; j++) bb[j] = b2[coloff + j];
    #pragma unroll
    for (int i = 0; i < 8; i++) {
        int e = m0 + rowoff + i;
        if (e >= EE) continue;
        int pos = g_pos[e];
        float o[8];
        #pragma unroll
        for (int j = 0; j < 8; j++) o[j] = fmaxf(acc[i][j] + bb[j], 0.f);
        *(float4*)&g_K2[pos * 256 + coloff]     = *(float4*)o;
        *(float4*)&g_K2[pos * 256 + coloff + 4] = *(float4*)(o + 4);
    }
}

// AW[j][c*32+i] = ker3_w[c][i*32+j]; AW[j][8192+i] = ker3_b[i*32+j]
__global__ void k_aw(const float* __restrict__ w3, const float* __restrict__ b3) {
    int idx = blockIdx.x * blockDim.x + threadIdx.x;
    if (idx >= 32 * ACOLS) return;
    int j = idx / ACOLS, r = idx % ACOLS;
    if (r < 8192) {
        int c = r >> 5, i = r & 31;
        g_AW[idx] = w3[c * 1024 + i * 32 + j];
    } else {
        int i = r - 8192;
        g_AW[idx] = b3[i * 32 + j];
    }
}

// A = H @ AW   [N,32]@[32,8224] — 64x256 tile
__global__ void __launch_bounds__(256) k_gemmA() {
    __shared__ float Hs[32 * HST];    // [k][node], stride 68 (float4-aligned)
    __shared__ float AWs[32 * 256];
    int tid = threadIdx.x;
    int m0 = blockIdx.y * 64;
    int n0 = blockIdx.x * 256;
    for (int i = tid; i < 2048; i += 256) {
        int node = i >> 5, k = i & 31;
        Hs[k * HST + node] = (m0 + node < NN) ? g_H[(m0 + node) * 32 + k] : 0.f;
    }
    const float4* AWf4 = (const float4*)g_AW;
    #pragma unroll
    for (int i = 0; i < 8; i++) {
        int idx = tid + i * 256;
        int kk = idx >> 6, c4 = idx & 63;
        int col = n0 + c4 * 4;
        float4 v = make_float4(0.f, 0.f, 0.f, 0.f);
        if (col < ACOLS) v = AWf4[kk * (ACOLS / 4) + (n0 >> 2) + c4];
        *(float4*)&AWs[kk * 256 + c4 * 4] = v;
    }
    __syncthreads();
    int wrp = tid >> 5, lane = tid & 31;
    int rowoff = (wrp >> 2) * 32 + (lane >> 3) * 8;
    int coloff = (wrp & 3) * 64 + (lane & 7) * 8;
    float acc[8][8];
    #pragma unroll
    for (int i = 0; i < 8; i++)
        #pragma unroll
        for (int j = 0; j < 8; j++) acc[i][j] = 0.f;
    #pragma unroll
    for (int kk = 0; kk < 32; kk++) {
        float a[8], b[8];
        *(float4*)a       = *(float4*)&Hs[kk * HST + rowoff];
        *(float4*)(a + 4) = *(float4*)&Hs[kk * HST + rowoff + 4];
        *(float4*)b       = *(float4*)&AWs[kk * 256 + coloff];
        *(float4*)(b + 4) = *(float4*)&AWs[kk * 256 + coloff + 4];
        #pragma unroll
        for (int i = 0; i < 8; i++)
            #pragma unroll
            for (int j = 0; j < 8; j++) acc[i][j] += a[i] * b[j];
    }
    int col = n0 + coloff;
    if (col < ACOLS) {
        #pragma unroll
        for (int i = 0; i < 8; i++) {
            int node = m0 + rowoff + i;
            if (node < NN) {
                *(float4*)&g_A[node * ACOLS + col]     = *(float4*)acc[i];
                *(float4*)&g_A[node * ACOLS + col + 4] = *(float4*)(acc[i] + 4);
            }
        }
    }
}

// fused M + coord-MLP + scatter: per col-bucket node.
// Thread tile: 2 edges x 4 cols. K2 read direct via LDG (no smem staging).
__global__ void __launch_bounds__(128) k_m(const float* __restrict__ cm1w,
                                           const float* __restrict__ cm1b,
                                           const float* __restrict__ cm2w,
                                           const float* __restrict__ cm2b) {
    extern __shared__ float sm[];
    float* As = sm;                  // ACOLS
    float* Ms = sm + ACOLS;          // 32*MST
    __shared__ float c1s[1024];
    __shared__ float c1bs[32], c2s[32];
    __shared__ float cn[3];
    __shared__ float cm2bv;
    int n = blockIdx.x;
    int beg = g_coloff[n];
    int nE = g_coloff[n + 1] - beg;
    if (nE == 0) return;
    int tid = threadIdx.x;
    for (int i = tid; i < 1024; i += 128) c1s[i] = cm1w[i];
    if (tid < 32) { c1bs[tid] = cm1b[tid]; c2s[tid] = cm2w[tid]; }
    if (tid < 3) cn[tid] = g_COORD[n * 3 + tid];
    if (tid == 4) cm2bv = cm2b[0];
    const float4* Af4 = (const float4*)&g_A[n * ACOLS];
    for (int i = tid; i < ACOLS / 4; i += 128) ((float4*)As)[i] = Af4[i];
    __syncthreads();

    int cg = tid & 7;                // col group: 4 cols
    int e0 = (tid >> 3) * 2;         // edge pair: e0, e0+1
    int lane = tid & 31, wrp = tid >> 5;

    for (int base = 0; base < nE; base += 32) {
        int cnt = min(32, nE - base);
        bool v0 = (e0 < cnt), v1 = (e0 + 1 < cnt);
        const float4* k0 = (const float4*)&g_K2[(size_t)(beg + base + e0) * 256];
        const float4* k1 = (const float4*)&g_K2[(size_t)(beg + base + e0 + 1) * 256];
        float4 bias = *(float4*)&As[8192 + cg * 4];
        float a00 = bias.x, a01 = bias.y, a02 = bias.z, a03 = bias.w;
        float a10 = bias.x, a11 = bias.y, a12 = bias.z, a13 = bias.w;
        if (v0) {
            #pragma unroll 4
            for (int c4 = 0; c4 < 64; c4++) {
                float4 ka = k0[c4];
                float4 kb = v1 ? k1[c4] : make_float4(0.f, 0.f, 0.f, 0.f);
                #pragma unroll
                for (int q = 0; q < 4; q++) {
                    float kva = (q == 0) ? ka.x : (q == 1) ? ka.y : (q == 2) ? ka.z : ka.w;
                    float kvb = (q == 0) ? kb.x : (q == 1) ? kb.y : (q == 2) ? kb.z : kb.w;
                    float4 av = *(float4*)&As[(c4 * 4 + q) * 32 + cg * 4];
                    a00 += kva * av.x; a01 += kva * av.y; a02 += kva * av.z; a03 += kva * av.w;
                    a10 += kvb * av.x; a11 += kvb * av.y; a12 += kvb * av.z; a13 += kvb * av.w;
                }
            }
            *(float4*)&Ms[e0 * MST + cg * 4] = make_float4(a00, a01, a02, a03);
            if (v1) *(float4*)&Ms[(e0 + 1) * MST + cg * 4] = make_float4(a10, a11, a12, a13);
        }
        __syncthreads();
        // MLP + scatter: 4 warps x 8 edges
        #pragma unroll 2
        for (int q = 0; q < 8; q++) {
            int es_ = wrp * 8 + q;
            if (es_ < cnt) {
                float mv = Ms[es_ * MST + lane];
                float t = c1bs[lane];
                #pragma unroll
                for (int j = 0; j < 32; j++)
                    t += __shfl_sync(0xffffffffu, mv, j) * c1s[j * 32 + lane];
                t = fmaxf(t, 0.f);
                float p = t * c2s[lane];
                #pragma unroll
                for (int off = 16; off > 0; off >>= 1)
                    p += __shfl_xor_sync(0xffffffffu, p, off);
                float we = p + cm2bv;
                int row = g_rows[beg + base + es_];
                atomicAdd(&g_AGG[row * 32 + lane], mv);
                if (lane < 3) {
                    float d = g_COORD[row * 3 + lane] - cn[lane];
                    atomicAdd(&g_CD[row * 3 + lane], d * we);
                }
            }
        }
        __syncthreads();
    }
}

__global__ void k_update() {
    int i = blockIdx.x * blockDim.x + threadIdx.x;
    if (i < NN * WD) {
        int n = i >> 5;
        float inv = 1.f / g_CNT[n];
        g_H[i] = fmaxf(g_H[i] + g_AGG[i] * inv, 0.f);
        g_AGG[i] = 0.f;
    }
    if (i < NN * 3) {
        int n = i / 3;
        g_COORD[i] += g_CD[i] / g_CNT[n];
        g_CD[i] = 0.f;
    }
}

__global__ void k_final(const float* __restrict__ f2aw, const float* __restrict__ f2ab,
                        const float* __restrict__ f2bw, const float* __restrict__ f2bb,
                        float* __restrict__ out) {
    __shared__ float wa[2048];
    __shared__ float ba[64];
    __shared__ float wb[64];
    int tid = threadIdx.x;
    for (int i = tid; i < 2048; i += 256) wa[i] = f2aw[i];
    if (tid < 64) { ba[tid] = f2ab[tid]; wb[tid] = f2bw[tid]; }
    __syncthreads();
    int n = blockIdx.x * blockDim.x + tid;
    if (n < NN) {
        float h[32];
        #pragma unroll
        for (int j = 0; j < 32; j++) h[j] = g_H[n * 32 + j];
        float o = f2bb[0];
        #pragma unroll 4
        for (int u = 0; u < 64; u++) {
            float s = ba[u];
            #pragma unroll
            for (int j = 0; j < 32; j++) s += h[j] * wa[j * 64 + u];
            o += fmaxf(s, 0.f) * wb[u];
        }
        out[n] = o;
    }
    int tot = gridDim.x * blockDim.x;
    for (int i = n; i < NN * 3; i += tot) out[NN + i] = g_COORD[i];
}

// ---------------- host ----------------
extern "C" void kernel_launch(void* const* d_in, const int* in_sizes, int n_in,
                              void* d_out, int out_size) {
    const float* x      = (const float*)d_in[0];
    const int*   ei     = (const int*)d_in[1];     // int32 (JAX x64 disabled)
    const float* ea     = (const float*)d_in[2];
    const float* coords = (const float*)d_in[3];
    const float* fc1w   = (const float*)d_in[4];
    const float* fc1b   = (const float*)d_in[5];
    const float* k1w    = (const float*)d_in[6];
    const float* k1b    = (const float*)d_in[7];
    const float* k2w    = (const float*)d_in[8];
    const float* k2b    = (const float*)d_in[9];
    const float* k3w    = (const float*)d_in[10];
    const float* k3b    = (const float*)d_in[11];
    const float* cm1w   = (const float*)d_in[12];
    const float* cm1b   = (const float*)d_in[13];
    const float* cm2w   = (const float*)d_in[14];
    const float* cm2b   = (const float*)d_in[15];
    const float* f2aw   = (const float*)d_in[16];
    const float* f2ab   = (const float*)d_in[17];
    const float* f2bw   = (const float*)d_in[18];
    const float* f2bb   = (const float*)d_in[19];

    const int smemM  = (ACOLS + 32 * MST) * 4;              // 37504 B
    const int smemG2 = (8192 + 16 * 256) * 4;               // 49152 B
    cudaFuncSetAttribute(k_m, cudaFuncAttributeMaxDynamicSharedMemorySize, smemM);
    cudaFuncSetAttribute(k_gemm2, cudaFuncAttributeMaxDynamicSharedMemorySize, smemG2);

    k_hist<<<(EE + 255) / 256, 256>>>(ei);
    k_scan<<<1, 1024>>>();
    k_scatter<<<(EE + 255) / 256, 256>>>(ei);
    k_gemm2<<<(EE + 63) / 64, 256, smemG2>>>(ea, k1w, k1b, k2w, k2b);
    k_init<<<(NN * WD + 255) / 256, 256>>>(x, coords, fc1w, fc1b);
    k_aw<<<(32 * ACOLS + 255) / 256, 256>>>(k3w, k3b);

    for (int d = 0; d < DEPTH; d++) {
        k_gemmA<<<dim3((ACOLS + 255) / 256, (NN + 63) / 64), 256>>>();
        k_m<<<NN, 128, smemM>>>(cm1w, cm1b, cm2w, cm2b);
        k_update<<<(NN * WD + 255) / 256, 256>>>();
    }
    k_final<<<(NN + 255) / 256, 256>>>(f2aw, f2ab, f2bw, f2bb, (float*)d_out);
    k_cleanup<<<(NN + 255) / 256, 256>>>();
}

// round 7
// speedup vs baseline: 1.0303x; 1.0303x over previous
#include <cuda_runtime.h>
#include <cstdint>

#define NN 10000
#define EE 300000
#define WD 32
#define DEPTH 4
#define ACOLS 8224           // 8192 (A) + 32 (bias part)
#define KST 260              // k2 smem row stride (float4-aligned, conflict-free)
#define MST 36               // m smem row stride
#define HST 68               // Hs stride: multiple of 4 (float4-aligned)

// ---------------- scratch (static __device__) ----------------
__device__ __align__(16) float g_K2[EE * 256];          // relu MLP out, PERMUTED by col-bucket
__device__ __align__(16) float g_A[NN * ACOLS];         // per-node A|bias
__device__ __align__(16) float g_AW[32 * ACOLS];        // transposed ker3 weights
__device__ __align__(16) float g_H[NN * WD];
__device__ __align__(16) float g_AGG[NN * WD];
__device__ __align__(16) float g_COORD[NN * 3];
__device__ __align__(16) float g_CD[NN * 3];
__device__ float g_CNT[NN];
__device__ int   g_colcnt[NN];
__device__ int   g_rowcnt[NN];
__device__ int   g_coloff[NN + 1];
__device__ int   g_cur[NN];
__device__ int   g_pos[EE];     // edge -> sorted position
__device__ int   g_rows[EE];    // sorted position -> row node

// ---------------- setup ----------------
__global__ void k_hist(const int* __restrict__ ei) {
    int e = blockIdx.x * blockDim.x + threadIdx.x;
    if (e < EE) {
        atomicAdd(&g_rowcnt[ei[e]], 1);
        atomicAdd(&g_colcnt[ei[EE + e]], 1);
    }
}

__global__ void k_scan() {
    __shared__ int sh[1024];
    __shared__ int carry;
    int t = threadIdx.x;
    if (t == 0) carry = 0;
    __syncthreads();
    for (int base = 0; base < NN; base += 1024) {
        int v = (base + t < NN) ? g_colcnt[base + t] : 0;
        sh[t] = v;
        __syncthreads();
        for (int off = 1; off < 1024; off <<= 1) {
            int y = (t >= off) ? sh[t - off] : 0;
            __syncthreads();
            sh[t] += y;
            __syncthreads();
        }
        int incl = sh[t];
        if (base + t < NN) {
            int ex = carry + incl - v;
            g_coloff[base + t] = ex;
            g_cur[base + t] = ex;
        }
        int tot = sh[1023];
        __syncthreads();
        if (t == 0) carry += tot;
        __syncthreads();
    }
    if (t == 0) g_coloff[NN] = carry;
}

__global__ void k_scatter(const int* __restrict__ ei) {
    int e = blockIdx.x * blockDim.x + threadIdx.x;
    if (e < EE) {
        int r = ei[e], c = ei[EE + e];
        int p = atomicAdd(&g_cur[c], 1);
        g_pos[e] = p;
        g_rows[p] = r;
    }
}

__global__ void k_init(const float* __restrict__ x, const float* __restrict__ coords,
                       const float* __restrict__ fc1w, const float* __restrict__ fc1b) {
    int i = blockIdx.x * blockDim.x + threadIdx.x;
    if (i < NN) g_CNT[i] = fmaxf(1.f, (float)g_rowcnt[i]);
    if (i < NN * 3) g_COORD[i] = coords[i];
    if (i < NN * WD) {
        int n = i / WD, o = i % WD;
        float a = fc1b[o];
        #pragma unroll
        for (int j = 0; j < 3; j++) a += x[n * 3 + j] * fc1w[j * WD + o];
        g_H[i] = a;
    }
}

__global__ void k_cleanup() {
    int i = blockIdx.x * blockDim.x + threadIdx.x;
    if (i < NN) { g_colcnt[i] = 0; g_rowcnt[i] = 0; }
}

// ---------------- fused kernel MLP: K2 = relu(relu(ea@W1+b1)@W2+b2), permuted write ----
// Thread tile: rows {ty*4..+3, 32+ty*4..+3}, cols {tx*4..+3, 128+tx*4..+3}
// -> all LDS.128 are lane-contiguous (conflict-free), all STG.128 coalesced.
__global__ void __launch_bounds__(256) k_gemm2(const float* __restrict__ ea,
                                               const float* __restrict__ w1,
                                               const float* __restrict__ b1,
                                               const float* __restrict__ w2,
                                               const float* __restrict__ b2) {
    extern __shared__ float s2[];
    float* R1t = s2;            // [128][64] k-major
    float* Bs  = s2 + 8192;     // [16][256]
    __shared__ float eas[64 * 6];
    __shared__ float w1s[6 * 128];
    __shared__ float b1s[128];
    int tid = threadIdx.x;
    int m0 = blockIdx.x * 64;

    for (int i = tid; i < 64 * 6; i += 256) {
        int g = m0 * 6 + i;
        eas[i] = (g < EE * 6) ? ea[g] : 0.f;
    }
    for (int i = tid; i < 768; i += 256) w1s[i] = w1[i];
    if (tid < 128) b1s[tid] = b1[tid];
    __syncthreads();

    // R1 tile: thread handles row r = tid&63, k-group tid>>6 (32 k's)
    {
        int r = tid & 63, kg = tid >> 6;
        float ev[6];
        #pragma unroll
        for (int j = 0; j < 6; j++) ev[j] = eas[r * 6 + j];
        #pragma unroll
        for (int q = 0; q < 32; q++) {
            int k = kg * 32 + q;
            float a = b1s[k];
            #pragma unroll
            for (int j = 0; j < 6; j++) a += ev[j] * w1s[j * 128 + k];
            R1t[k * 64 + r] = fmaxf(a, 0.f);
        }
    }
    __syncthreads();

    int tx = tid & 31, ty = tid >> 5;
    int r0 = ty * 4, r1 = 32 + ty * 4;       // row groups
    int c0 = tx * 4, c1 = 128 + tx * 4;      // col groups
    float acc[8][8];
    #pragma unroll
    for (int i = 0; i < 8; i++)
        #pragma unroll
        for (int j = 0; j < 8; j++) acc[i][j] = 0.f;

    for (int kc = 0; kc < 128; kc += 16) {
        #pragma unroll
        for (int i = 0; i < 4; i++) {
            int idx = tid + i * 256;
            int kk = idx >> 6, c4 = idx & 63;
            *(float4*)&Bs[kk * 256 + c4 * 4] = *(const float4*)&w2[(kc + kk) * 256 + c4 * 4];
        }
        __syncthreads();
        #pragma unroll
        for (int kk = 0; kk < 16; kk++) {
            float a[8], b[8];
            *(float4*)a       = *(float4*)&R1t[(kc + kk) * 64 + r0];
            *(float4*)(a + 4) = *(float4*)&R1t[(kc + kk) * 64 + r1];
            *(float4*)b       = *(float4*)&Bs[kk * 256 + c0];
            *(float4*)(b + 4) = *(float4*)&Bs[kk * 256 + c1];
            #pragma unroll
            for (int i = 0; i < 8; i++)
                #pragma unroll
                for (int j = 0; j < 8; j++) acc[i][j] += a[i] * b[j];
        }
        __syncthreads();
    }
    float bb[8];
    #pragma unroll
    for (int j = 0; j < 4; j++) { bb[j] = b2[c0 + j]; bb[4 + j] = b2[c1 + j]; }
    #pragma unroll
    for (int half = 0; half < 2; half++) {
        int rbase = (half == 0) ? r0 : r1;
        #pragma unroll
        for (int i = 0; i < 4; i++) {
            int e = m0 + rbase + i;
            if (e >= EE) continue;
            int pos = g_pos[e];
            int ai = half * 4 + i;
            float o[8];
            #pragma unroll
            for (int j = 0; j < 8; j++) o[j] = fmaxf(acc[ai][j] + bb[j], 0.f);
            *(float4*)&g_K2[pos * 256 + c0] = *(float4*)o;
            *(float4*)&g_K2[pos * 256 + c1] = *(float4*)(o + 4);
        }
    }
}

// AW[j][c*32+i] = ker3_w[c][i*32+j]; AW[j][8192+i] = ker3_b[i*32+j]
__global__ void k_aw(const float* __restrict__ w3, const float* __restrict__ b3) {
    int idx = blockIdx.x * blockDim.x + threadIdx.x;
    if (idx >= 32 * ACOLS) return;
    int j = idx / ACOLS, r = idx % ACOLS;
    if (r < 8192) {
        int c = r >> 5, i = r & 31;
        g_AW[idx] = w3[c * 1024 + i * 32 + j];
    } else {
        int i = r - 8192;
        g_AW[idx] = b3[i * 32 + j];
    }
}

// A = H @ AW   [N,32]@[32,8224] — 64x256 tile, conflict-free thread tiling
__global__ void __launch_bounds__(256) k_gemmA() {
    __shared__ float Hs[32 * HST];    // [k][node], stride 68 (float4-aligned)
    __shared__ float AWs[32 * 256];
    int tid = threadIdx.x;
    int m0 = blockIdx.y * 64;
    int n0 = blockIdx.x * 256;
    for (int i = tid; i < 2048; i += 256) {
        int node = i >> 5, k = i & 31;
        Hs[k * HST + node] = (m0 + node < NN) ? g_H[(m0 + node) * 32 + k] : 0.f;
    }
    const float4* AWf4 = (const float4*)g_AW;
    #pragma unroll
    for (int i = 0; i < 8; i++) {
        int idx = tid + i * 256;
        int kk = idx >> 6, c4 = idx & 63;
        int col = n0 + c4 * 4;
        float4 v = make_float4(0.f, 0.f, 0.f, 0.f);
        if (col < ACOLS) v = AWf4[kk * (ACOLS / 4) + (n0 >> 2) + c4];
        *(float4*)&AWs[kk * 256 + c4 * 4] = v;
    }
    __syncthreads();
    int tx = tid & 31, ty = tid >> 5;
    int r0 = ty * 4, r1 = 32 + ty * 4;
    int c0 = tx * 4, c1 = 128 + tx * 4;
    float acc[8][8];
    #pragma unroll
    for (int i = 0; i < 8; i++)
        #pragma unroll
        for (int j = 0; j < 8; j++) acc[i][j] = 0.f;
    #pragma unroll
    for (int kk = 0; kk < 32; kk++) {
        float a[8], b[8];
        *(float4*)a       = *(float4*)&Hs[kk * HST + r0];
        *(float4*)(a + 4) = *(float4*)&Hs[kk * HST + r1];
        *(float4*)b       = *(float4*)&AWs[kk * 256 + c0];
        *(float4*)(b + 4) = *(float4*)&AWs[kk * 256 + c1];
        #pragma unroll
        for (int i = 0; i < 8; i++)
            #pragma unroll
            for (int j = 0; j < 8; j++) acc[i][j] += a[i] * b[j];
    }
    #pragma unroll
    for (int half = 0; half < 2; half++) {
        int rbase = (half == 0) ? r0 : r1;
        #pragma unroll
        for (int i = 0; i < 4; i++) {
            int node = m0 + rbase + i;
            if (node >= NN) continue;
            int ai = half * 4 + i;
            if (n0 + c0 < ACOLS)
                *(float4*)&g_A[node * ACOLS + n0 + c0] = *(float4*)acc[ai];
            if (n0 + c1 < ACOLS)
                *(float4*)&g_A[node * ACOLS + n0 + c1] = *(float4*)(acc[ai] + 4);
        }
    }
}

// fused M + coord-MLP + scatter: per col-bucket node (K2 staged once in smem)
__global__ void __launch_bounds__(128) k_m(const float* __restrict__ cm1w,
                                           const float* __restrict__ cm1b,
                                           const float* __restrict__ cm2w,
                                           const float* __restrict__ cm2b) {
    extern __shared__ float sm[];
    float* As = sm;                  // ACOLS
    float* Ks = sm + ACOLS;          // 32*KST
    float* Ms = Ks + 32 * KST;       // 32*MST
    __shared__ float c1s[1024];
    __shared__ float c1bs[32], c2s[32];
    __shared__ float cn[3];
    __shared__ float cm2bv;
    int n = blockIdx.x;
    int beg = g_coloff[n];
    int nE = g_coloff[n + 1] - beg;
    if (nE == 0) return;
    int tid = threadIdx.x;
    for (int i = tid; i < 1024; i += 128) c1s[i] = cm1w[i];
    if (tid < 32) { c1bs[tid] = cm1b[tid]; c2s[tid] = cm2w[tid]; }
    if (tid < 3) cn[tid] = g_COORD[n * 3 + tid];
    if (tid == 4) cm2bv = cm2b[0];
    const float4* Af4 = (const float4*)&g_A[n * ACOLS];
    for (int i = tid; i < ACOLS / 4; i += 128) ((float4*)As)[i] = Af4[i];
    int colgrp = tid & 3, eslot = tid >> 2;
    int lane = tid & 31, wrp = tid >> 5;

    for (int base = 0; base < nE; base += 32) {
        int cnt = min(32, nE - base);
        const float4* Kf4 = (const float4*)&g_K2[(size_t)(beg + base) * 256];
        for (int i = tid; i < cnt * 64; i += 128) {
            int el = i >> 6, c4 = i & 63;
            *(float4*)&Ks[el * KST + c4 * 4] = Kf4[i];
        }
        __syncthreads();
        if (eslot < cnt) {
            float acc[8];
            *(float4*)acc       = *(float4*)&As[8192 + colgrp * 8];
            *(float4*)(acc + 4) = *(float4*)&As[8192 + colgrp * 8 + 4];
            const float* kr = &Ks[eslot * KST];
            #pragma unroll 8
            for (int c = 0; c < 256; c++) {
                float kv = kr[c];
                float4 a0 = *(float4*)&As[c * 32 + colgrp * 8];
                float4 a1 = *(float4*)&As[c * 32 + colgrp * 8 + 4];
                acc[0] += kv * a0.x; acc[1] += kv * a0.y;
                acc[2] += kv * a0.z; acc[3] += kv * a0.w;
                acc[4] += kv * a1.x; acc[5] += kv * a1.y;
                acc[6] += kv * a1.z; acc[7] += kv * a1.w;
            }
            *(float4*)&Ms[eslot * MST + colgrp * 8]     = *(float4*)acc;
            *(float4*)&Ms[eslot * MST + colgrp * 8 + 4] = *(float4*)(acc + 4);
        }
        __syncthreads();
        // MLP + scatter: 4 warps x 8 edges
        #pragma unroll 2
        for (int q = 0; q < 8; q++) {
            int es_ = wrp * 8 + q;
            if (es_ < cnt) {
                float mv = Ms[es_ * MST + lane];
                float t = c1bs[lane];
                #pragma unroll
                for (int j = 0; j < 32; j++)
                    t += __shfl_sync(0xffffffffu, mv, j) * c1s[j * 32 + lane];
                t = fmaxf(t, 0.f);
                float p = t * c2s[lane];
                #pragma unroll
                for (int off = 16; off > 0; off >>= 1)
                    p += __shfl_xor_sync(0xffffffffu, p, off);
                float we = p + cm2bv;
                int row = g_rows[beg + base + es_];
                atomicAdd(&g_AGG[row * 32 + lane], mv);
                if (lane < 3) {
                    float d = g_COORD[row * 3 + lane] - cn[lane];
                    atomicAdd(&g_CD[row * 3 + lane], d * we);
                }
            }
        }
        __syncthreads();
    }
}

__global__ void k_update() {
    int i = blockIdx.x * blockDim.x + threadIdx.x;
    if (i < NN * WD) {
        int n = i >> 5;
        float inv = 1.f / g_CNT[n];
        g_H[i] = fmaxf(g_H[i] + g_AGG[i] * inv, 0.f);
        g_AGG[i] = 0.f;
    }
    if (i < NN * 3) {
        int n = i / 3;
        g_COORD[i] += g_CD[i] / g_CNT[n];
        g_CD[i] = 0.f;
    }
}

__global__ void k_final(const float* __restrict__ f2aw, const float* __restrict__ f2ab,
                        const float* __restrict__ f2bw, const float* __restrict__ f2bb,
                        float* __restrict__ out) {
    __shared__ float wa[2048];
    __shared__ float ba[64];
    __shared__ float wb[64];
    int tid = threadIdx.x;
    for (int i = tid; i < 2048; i += 256) wa[i] = f2aw[i];
    if (tid < 64) { ba[tid] = f2ab[tid]; wb[tid] = f2bw[tid]; }
    __syncthreads();
    int n = blockIdx.x * blockDim.x + tid;
    if (n < NN) {
        float h[32];
        #pragma unroll
        for (int j = 0; j < 32; j++) h[j] = g_H[n * 32 + j];
        float o = f2bb[0];
        #pragma unroll 4
        for (int u = 0; u < 64; u++) {
            float s = ba[u];
            #pragma unroll
            for (int j = 0; j < 32; j++) s += h[j] * wa[j * 64 + u];
            o += fmaxf(s, 0.f) * wb[u];
        }
        out[n] = o;
    }
    int tot = gridDim.x * blockDim.x;
    for (int i = n; i < NN * 3; i += tot) out[NN + i] = g_COORD[i];
}

// ---------------- host ----------------
extern "C" void kernel_launch(void* const* d_in, const int* in_sizes, int n_in,
                              void* d_out, int out_size) {
    const float* x      = (const float*)d_in[0];
    const int*   ei     = (const int*)d_in[1];     // int32 (JAX x64 disabled)
    const float* ea     = (const float*)d_in[2];
    const float* coords = (const float*)d_in[3];
    const float* fc1w   = (const float*)d_in[4];
    const float* fc1b   = (const float*)d_in[5];
    const float* k1w    = (const float*)d_in[6];
    const float* k1b    = (const float*)d_in[7];
    const float* k2w    = (const float*)d_in[8];
    const float* k2b    = (const float*)d_in[9];
    const float* k3w    = (const float*)d_in[10];
    const float* k3b    = (const float*)d_in[11];
    const float* cm1w   = (const float*)d_in[12];
    const float* cm1b   = (const float*)d_in[13];
    const float* cm2w   = (const float*)d_in[14];
    const float* cm2b   = (const float*)d_in[15];
    const float* f2aw   = (const float*)d_in[16];
    const float* f2ab   = (const float*)d_in[17];
    const float* f2bw   = (const float*)d_in[18];
    const float* f2bb   = (const float*)d_in[19];

    const int smemM  = (ACOLS + 32 * KST + 32 * MST) * 4;   // 70784 B
    const int smemG2 = (8192 + 16 * 256) * 4;               // 49152 B
    cudaFuncSetAttribute(k_m, cudaFuncAttributeMaxDynamicSharedMemorySize, smemM);
    cudaFuncSetAttribute(k_gemm2, cudaFuncAttributeMaxDynamicSharedMemorySize, smemG2);

    k_hist<<<(EE + 255) / 256, 256>>>(ei);
    k_scan<<<1, 1024>>>();
    k_scatter<<<(EE + 255) / 256, 256>>>(ei);
    k_gemm2<<<(EE + 63) / 64, 256, smemG2>>>(ea, k1w, k1b, k2w, k2b);
    k_init<<<(NN * WD + 255) / 256, 256>>>(x, coords, fc1w, fc1b);
    k_aw<<<(32 * ACOLS + 255) / 256, 256>>>(k3w, k3b);

    for (int d = 0; d < DEPTH; d++) {
        k_gemmA<<<dim3((ACOLS + 255) / 256, (NN + 63) / 64), 256>>>();
        k_m<<<NN, 128, smemM>>>(cm1w, cm1b, cm2w, cm2b);
        k_update<<<(NN * WD + 255) / 256, 256>>>();
    }
    k_final<<<(NN + 255) / 256, 256>>>(f2aw, f2ab, f2bw, f2bb, (float*)d_out);
    k_cleanup<<<(NN + 255) / 256, 256>>>();
}